// round 3
// baseline (speedup 1.0000x reference)
#include <cuda_runtime.h>

#define NNODES 8192
#define CDIM   64
#define HBITS  19
#define HSIZE  (1 << HBITS)
#define HMASK  (HSIZE - 1)
#define EMAX   262144

// ---------------- device scratch ----------------
__device__ int   g_hkey[HSIZE];
__device__ int   g_hval[HSIZE];
__device__ int   g_eslot[EMAX];
__device__ float g_deg[NNODES];
__device__ float g_s[NNODES];
__device__ int   g_rcnt[NNODES];
__device__ int   g_rfill[NNODES];
__device__ int   g_rptr[NNODES + 1];
__device__ int2  g_pack[EMAX];              // {col, weight-bits} interleaved
__device__ float g_t1[NNODES * CDIM];
__device__ float g_t2[NNODES * CDIM];
__device__ float g_sig;

// ---------------- init: vectorized hash clear + per-node state + sigmoid ----------------
__global__ void k_init(const float* __restrict__ aw) {
    int i = blockIdx.x * blockDim.x + threadIdx.x;
    int4 m1 = make_int4(-1, -1, -1, -1);
    if (i < HSIZE / 4) {
        ((int4*)g_hkey)[i] = m1;
        ((int4*)g_hval)[i] = m1;
    }
    if (i < NNODES) { g_deg[i] = 1.0f; g_rcnt[i] = 0; g_rfill[i] = 0; }
    if (i == 0) g_sig = 1.0f / (1.0f + expf(-aw[0]));
}

// ---------------- hash insert: dedup cells, last edge id wins; record slot ----------------
__global__ void k_insert(const int* __restrict__ ei, int E) {
    int e = blockIdx.x * blockDim.x + threadIdx.x;
    if (e >= E) return;
    int row = ei[e];
    int col = ei[E + e];
    int key = (row << 13) | col;
    int slot = (int)(((unsigned)key * 2654435761u) >> (32 - HBITS));
    while (true) {
        int k = g_hkey[slot];
        if (k == key) break;
        if (k == -1) {
            int old = atomicCAS(&g_hkey[slot], -1, key);
            if (old == -1 || old == key) break;
        }
        slot = (slot + 1) & HMASK;
    }
    g_eslot[e] = slot;
    atomicMax(&g_hval[slot], e);   // last-write-wins semantics
}

// ---------------- degree + row counts, edge-parallel over winners ----------------
__global__ void k_deg(const float* __restrict__ ew, int E) {
    int e = blockIdx.x * blockDim.x + threadIdx.x;
    if (e >= E) return;
    int slot = g_eslot[e];
    if (g_hval[slot] != e) return;          // lost dedup race: skip
    int row = g_hkey[slot] >> 13;
    atomicAdd(&g_deg[row], ew[e] * g_sig);
    atomicAdd(&g_rcnt[row], 1);
}

// ---------------- exclusive scan of row counts + fused rsqrt ----------------
__global__ void k_scan() {
    __shared__ int sums[1024];
    int t = threadIdx.x;
    int base = t * 8;
    int local[8];
    int s = 0;
    #pragma unroll
    for (int j = 0; j < 8; j++) {
        local[j] = s; s += g_rcnt[base + j];
        g_s[base + j] = rsqrtf(g_deg[base + j]);   // deg >= 1, never inf
    }
    sums[t] = s;
    __syncthreads();
    for (int off = 1; off < 1024; off <<= 1) {
        int v = (t >= off) ? sums[t - off] : 0;
        __syncthreads();
        sums[t] += v;
        __syncthreads();
    }
    int offset = (t == 0) ? 0 : sums[t - 1];
    #pragma unroll
    for (int j = 0; j < 8; j++) g_rptr[base + j] = offset + local[j];
    if (t == 1023) g_rptr[NNODES] = sums[1023];
}

// ---------------- CSR fill (packed col+weight), edge-parallel over winners ----------------
__global__ void k_fill(const float* __restrict__ ew, int E) {
    int e = blockIdx.x * blockDim.x + threadIdx.x;
    if (e >= E) return;
    int slot = g_eslot[e];
    if (g_hval[slot] != e) return;
    int key = g_hkey[slot];
    int row = key >> 13;
    int col = key & (NNODES - 1);
    float w = ew[e] * g_sig * g_s[row] * g_s[col];
    int pos = g_rptr[row] + atomicAdd(&g_rfill[row], 1);
    g_pack[pos] = make_int2(col, __float_as_int(w));
}

// ---------------- sparse apply: t1 = L x ----------------
// L v = (1 - s_i^2) v_i - sum_edges w_norm * v_j
__global__ void k_spmv1(const float* __restrict__ x) {
    int row = blockIdx.x * 4 + threadIdx.y;
    int c = threadIdx.x;
    int start = g_rptr[row], end = g_rptr[row + 1];
    float acc = 0.0f;
    int j = start;
    for (; j + 4 <= end; j += 4) {
        int2 p0 = g_pack[j],     p1 = g_pack[j + 1];
        int2 p2 = g_pack[j + 2], p3 = g_pack[j + 3];
        float v0 = __ldg(&x[p0.x * CDIM + c]);
        float v1 = __ldg(&x[p1.x * CDIM + c]);
        float v2 = __ldg(&x[p2.x * CDIM + c]);
        float v3 = __ldg(&x[p3.x * CDIM + c]);
        acc = fmaf(__int_as_float(p0.y), v0, acc);
        acc = fmaf(__int_as_float(p1.y), v1, acc);
        acc = fmaf(__int_as_float(p2.y), v2, acc);
        acc = fmaf(__int_as_float(p3.y), v3, acc);
    }
    for (; j < end; j++) {
        int2 p = g_pack[j];
        acc = fmaf(__int_as_float(p.y), __ldg(&x[p.x * CDIM + c]), acc);
    }
    float si = g_s[row];
    float d = 1.0f - si * si;
    int o = row * CDIM + c;
    g_t1[o] = d * x[o] - acc;
}

// ---------------- t2 = 2 * L t1 - x ----------------
__global__ void k_spmv2(const float* __restrict__ x) {
    int row = blockIdx.x * 4 + threadIdx.y;
    int c = threadIdx.x;
    int start = g_rptr[row], end = g_rptr[row + 1];
    float acc = 0.0f;
    int j = start;
    for (; j + 4 <= end; j += 4) {
        int2 p0 = g_pack[j],     p1 = g_pack[j + 1];
        int2 p2 = g_pack[j + 2], p3 = g_pack[j + 3];
        float v0 = __ldg(&g_t1[p0.x * CDIM + c]);
        float v1 = __ldg(&g_t1[p1.x * CDIM + c]);
        float v2 = __ldg(&g_t1[p2.x * CDIM + c]);
        float v3 = __ldg(&g_t1[p3.x * CDIM + c]);
        acc = fmaf(__int_as_float(p0.y), v0, acc);
        acc = fmaf(__int_as_float(p1.y), v1, acc);
        acc = fmaf(__int_as_float(p2.y), v2, acc);
        acc = fmaf(__int_as_float(p3.y), v3, acc);
    }
    for (; j < end; j++) {
        int2 p = g_pack[j];
        acc = fmaf(__int_as_float(p.y), __ldg(&g_t1[p.x * CDIM + c]), acc);
    }
    float si = g_s[row];
    float d = 1.0f - si * si;
    int o = row * CDIM + c;
    g_t2[o] = 2.0f * (d * g_t1[o] - acc) - x[o];
}

// ---------------- epilogue GEMM: out = x W0 + t1 W1 + t2 W2 + b ----------------
__global__ void k_gemm(const float* __restrict__ x, const float* __restrict__ W,
                       const float* __restrict__ bias, float* __restrict__ out) {
    __shared__ float Ws[3 * 64 * 64];   // 48 KB
    for (int i = threadIdx.x; i < 3 * 64 * 64; i += 256) Ws[i] = W[i];
    __syncthreads();
    int c = threadIdx.x & 63;
    int rg = threadIdx.x >> 6;          // 0..3
    int row0 = blockIdx.x * 64 + rg * 16;
    for (int r = row0; r < row0 + 16; r++) {
        const float* xr  = x    + r * 64;
        const float* t1r = g_t1 + r * 64;
        const float* t2r = g_t2 + r * 64;
        float acc = __ldg(&bias[c]);
        #pragma unroll 8
        for (int k = 0; k < 64; k++) {
            acc += __ldg(&xr[k])  * Ws[k * 64 + c];
            acc += __ldg(&t1r[k]) * Ws[4096 + k * 64 + c];
            acc += __ldg(&t2r[k]) * Ws[8192 + k * 64 + c];
        }
        out[r * 64 + c] = acc;
    }
}

// ---------------- launch ----------------
extern "C" void kernel_launch(void* const* d_in, const int* in_sizes, int n_in,
                              void* d_out, int out_size) {
    const float* x    = (const float*)d_in[0];
    const int*   ei   = (const int*)d_in[1];       // int32 (JAX x64 disabled)
    const float* ew   = (const float*)d_in[2];
    const float* W    = (const float*)d_in[3];
    const float* aw   = (const float*)d_in[4];
    const float* bias = (const float*)d_in[5];
    float* out = (float*)d_out;
    int E = in_sizes[2];

    dim3 spmvBlk(64, 4);
    k_init  <<<HSIZE / 4 / 256, 256>>>(aw);
    k_insert<<<(E + 255) / 256, 256>>>(ei, E);
    k_deg   <<<(E + 255) / 256, 256>>>(ew, E);
    k_scan  <<<1, 1024>>>();
    k_fill  <<<(E + 255) / 256, 256>>>(ew, E);
    k_spmv1 <<<NNODES / 4, spmvBlk>>>(x);
    k_spmv2 <<<NNODES / 4, spmvBlk>>>(x);
    k_gemm  <<<NNODES / 64, 256>>>(x, W, bias, out);
}

// round 15
// speedup vs baseline: 1.3770x; 1.3770x over previous
#include <cuda_runtime.h>

#define NNODES 8192
#define CDIM   64
#define HBITS  19
#define HSIZE  (1 << HBITS)
#define HMASK  (HSIZE - 1)
#define EMAX   262144

// ---------------- device scratch ----------------
__device__ int   g_hkey[HSIZE];
__device__ int   g_hval[HSIZE];
__device__ int   g_eslot[EMAX];
__device__ float g_deg[NNODES];
__device__ int   g_rcnt[NNODES];
__device__ int   g_rfill[NNODES];
__device__ int   g_rptr[NNODES + 1];
__device__ int2  g_pack[EMAX];              // {col, weight-bits}
__device__ float g_t1[NNODES * CDIM];
__device__ float g_t2[NNODES * CDIM];
__device__ float g_sig;

// ---------------- init ----------------
__global__ void k_init(const float* __restrict__ aw) {
    int i = blockIdx.x * blockDim.x + threadIdx.x;
    int4 m1 = make_int4(-1, -1, -1, -1);
    if (i < HSIZE / 4) {
        ((int4*)g_hkey)[i] = m1;
        ((int4*)g_hval)[i] = m1;
    }
    if (i < NNODES) { g_deg[i] = 1.0f; g_rcnt[i] = 0; g_rfill[i] = 0; }
    if (i == 0) g_sig = 1.0f / (1.0f + expf(-aw[0]));
}

// ---------------- hash insert: dedup, last edge id wins; creator counts row ----------------
__global__ void k_insert(const int* __restrict__ ei, int E) {
    int e = blockIdx.x * blockDim.x + threadIdx.x;
    if (e >= E) return;
    int row = ei[e];
    int col = ei[E + e];
    int key = (row << 13) | col;
    int slot = (int)(((unsigned)key * 2654435761u) >> (32 - HBITS));
    while (true) {
        int k = g_hkey[slot];
        if (k == key) break;
        if (k == -1) {
            int old = atomicCAS(&g_hkey[slot], -1, key);
            if (old == -1) { atomicAdd(&g_rcnt[row], 1); break; }  // unique cell created
            if (old == key) break;
        }
        slot = (slot + 1) & HMASK;
    }
    g_eslot[e] = slot;
    atomicMax(&g_hval[slot], e);   // last-write-wins
}

// ---------------- exclusive scan of row counts (shuffle-based, 1 block) ----------------
__global__ void k_scan() {
    __shared__ int wsum[32];
    int t = threadIdx.x;
    int lane = t & 31, wid = t >> 5;
    int base = t * 8;
    int local[8];
    int4 a = ((int4*)g_rcnt)[t * 2];
    int4 b = ((int4*)g_rcnt)[t * 2 + 1];
    int s = 0;
    local[0] = s; s += a.x; local[1] = s; s += a.y;
    local[2] = s; s += a.z; local[3] = s; s += a.w;
    local[4] = s; s += b.x; local[5] = s; s += b.y;
    local[6] = s; s += b.z; local[7] = s; s += b.w;
    int v = s;
    int incl = v;
    #pragma unroll
    for (int off = 1; off < 32; off <<= 1) {
        int n = __shfl_up_sync(0xffffffffu, incl, off);
        if (lane >= off) incl += n;
    }
    if (lane == 31) wsum[wid] = incl;
    __syncthreads();
    if (wid == 0) {
        int wv = wsum[lane];
        int winc = wv;
        #pragma unroll
        for (int off = 1; off < 32; off <<= 1) {
            int n = __shfl_up_sync(0xffffffffu, winc, off);
            if (lane >= off) winc += n;
        }
        wsum[lane] = winc - wv;    // exclusive warp offsets
    }
    __syncthreads();
    int threadBase = wsum[wid] + incl - v;   // exclusive prefix of this thread
    #pragma unroll
    for (int j = 0; j < 8; j++) g_rptr[base + j] = threadBase + local[j];
    if (t == 1023) g_rptr[NNODES] = threadBase + v;
}

// ---------------- degree accumulation over winner edges ----------------
__global__ void k_deg(const float* __restrict__ ew, int E) {
    int e = blockIdx.x * blockDim.x + threadIdx.x;
    if (e >= E) return;
    int slot = g_eslot[e];
    if (g_hval[slot] != e) return;          // not the winner for this cell
    int row = g_hkey[slot] >> 13;
    atomicAdd(&g_deg[row], ew[e] * g_sig);
}

// ---------------- CSR fill (packed col+weight); rsqrt on the fly ----------------
__global__ void k_fill(const float* __restrict__ ew, int E) {
    int e = blockIdx.x * blockDim.x + threadIdx.x;
    if (e >= E) return;
    int slot = g_eslot[e];
    if (g_hval[slot] != e) return;
    int key = g_hkey[slot];
    int row = key >> 13;
    int col = key & (NNODES - 1);
    float w = ew[e] * g_sig * rsqrtf(g_deg[row]) * rsqrtf(g_deg[col]);
    int pos = g_rptr[row] + atomicAdd(&g_rfill[row], 1);
    g_pack[pos] = make_int2(col, __float_as_int(w));
}

// ---------------- spmv core: acc = sum_j w_j * src[col_j*64 + c], 8-deep MLP ----------------
// int2 pack loads only (LDG.64, any alignment) — trap-proof; MLP from 8 independent gathers.
__device__ __forceinline__ float row_gather(const float* __restrict__ src,
                                            int start, int end, int c) {
    float acc = 0.0f;
    int j = start;
    for (; j + 8 <= end; j += 8) {
        int2 p0 = g_pack[j],     p1 = g_pack[j + 1];
        int2 p2 = g_pack[j + 2], p3 = g_pack[j + 3];
        int2 p4 = g_pack[j + 4], p5 = g_pack[j + 5];
        int2 p6 = g_pack[j + 6], p7 = g_pack[j + 7];
        float v0 = __ldg(&src[p0.x * CDIM + c]);
        float v1 = __ldg(&src[p1.x * CDIM + c]);
        float v2 = __ldg(&src[p2.x * CDIM + c]);
        float v3 = __ldg(&src[p3.x * CDIM + c]);
        float v4 = __ldg(&src[p4.x * CDIM + c]);
        float v5 = __ldg(&src[p5.x * CDIM + c]);
        float v6 = __ldg(&src[p6.x * CDIM + c]);
        float v7 = __ldg(&src[p7.x * CDIM + c]);
        acc = fmaf(__int_as_float(p0.y), v0, acc);
        acc = fmaf(__int_as_float(p1.y), v1, acc);
        acc = fmaf(__int_as_float(p2.y), v2, acc);
        acc = fmaf(__int_as_float(p3.y), v3, acc);
        acc = fmaf(__int_as_float(p4.y), v4, acc);
        acc = fmaf(__int_as_float(p5.y), v5, acc);
        acc = fmaf(__int_as_float(p6.y), v6, acc);
        acc = fmaf(__int_as_float(p7.y), v7, acc);
    }
    for (; j < end; j++) {
        int2 p = g_pack[j];
        acc = fmaf(__int_as_float(p.y), __ldg(&src[p.x * CDIM + c]), acc);
    }
    return acc;
}

// ---------------- sparse apply: t1 = L x ----------------
// L v = (1 - 1/deg_i) v_i - sum_edges w_norm * v_j
__global__ void k_spmv1(const float* __restrict__ x) {
    int row = blockIdx.x * 4 + threadIdx.y;
    int c = threadIdx.x;
    float acc = row_gather(x, g_rptr[row], g_rptr[row + 1], c);
    float d = 1.0f - 1.0f / g_deg[row];
    int o = row * CDIM + c;
    g_t1[o] = d * x[o] - acc;
}

// ---------------- t2 = 2 * L t1 - x ----------------
__global__ void k_spmv2(const float* __restrict__ x) {
    int row = blockIdx.x * 4 + threadIdx.y;
    int c = threadIdx.x;
    float acc = row_gather(g_t1, g_rptr[row], g_rptr[row + 1], c);
    float d = 1.0f - 1.0f / g_deg[row];
    int o = row * CDIM + c;
    g_t2[o] = 2.0f * (d * g_t1[o] - acc) - x[o];
}

// ---------------- epilogue GEMM: out = [x|t1|t2] @ [W0;W1;W2] + b ----------------
// block = 256 threads: 16 rows x 16 col-groups (4 cols each, float4).
__global__ void k_gemm(const float* __restrict__ x, const float* __restrict__ W,
                       const float* __restrict__ bias, float* __restrict__ out) {
    __shared__ float Ws[192 * 64];      // 48 KB
    __shared__ float As[16][192];       // 12 KB, 768B row pitch (16B aligned)
    int t = threadIdx.x;
    int row0 = blockIdx.x * 16;

    // stage W (float4, coalesced)
    for (int i = t; i < 192 * 64 / 4; i += 256)
        ((float4*)Ws)[i] = ((const float4*)W)[i];
    // stage 16 rows of x|t1|t2 (each row: 16+16+16 float4)
    for (int i = t; i < 16 * 48; i += 256) {
        int r = i / 48, seg = i % 48;
        const float* src = (seg < 16) ? &x[(row0 + r) * 64 + seg * 4]
                         : (seg < 32) ? &g_t1[(row0 + r) * 64 + (seg - 16) * 4]
                                      : &g_t2[(row0 + r) * 64 + (seg - 32) * 4];
        ((float4*)&As[r][0])[seg] = *(const float4*)src;
    }
    __syncthreads();

    int rg = t >> 4;        // 0..15 row within tile
    int cg = t & 15;        // 0..15 col group
    float4 acc = *(const float4*)&bias[cg * 4];
    #pragma unroll
    for (int k4 = 0; k4 < 48; k4++) {
        float4 a = ((float4*)&As[rg][0])[k4];
        float4 w0 = *(float4*)&Ws[(k4 * 4 + 0) * 64 + cg * 4];
        float4 w1 = *(float4*)&Ws[(k4 * 4 + 1) * 64 + cg * 4];
        float4 w2 = *(float4*)&Ws[(k4 * 4 + 2) * 64 + cg * 4];
        float4 w3 = *(float4*)&Ws[(k4 * 4 + 3) * 64 + cg * 4];
        acc.x = fmaf(a.x, w0.x, acc.x); acc.y = fmaf(a.x, w0.y, acc.y);
        acc.z = fmaf(a.x, w0.z, acc.z); acc.w = fmaf(a.x, w0.w, acc.w);
        acc.x = fmaf(a.y, w1.x, acc.x); acc.y = fmaf(a.y, w1.y, acc.y);
        acc.z = fmaf(a.y, w1.z, acc.z); acc.w = fmaf(a.y, w1.w, acc.w);
        acc.x = fmaf(a.z, w2.x, acc.x); acc.y = fmaf(a.z, w2.y, acc.y);
        acc.z = fmaf(a.z, w2.z, acc.z); acc.w = fmaf(a.z, w2.w, acc.w);
        acc.x = fmaf(a.w, w3.x, acc.x); acc.y = fmaf(a.w, w3.y, acc.y);
        acc.z = fmaf(a.w, w3.z, acc.z); acc.w = fmaf(a.w, w3.w, acc.w);
    }
    *(float4*)&out[(row0 + rg) * 64 + cg * 4] = acc;
}

// ---------------- launch ----------------
extern "C" void kernel_launch(void* const* d_in, const int* in_sizes, int n_in,
                              void* d_out, int out_size) {
    const float* x    = (const float*)d_in[0];
    const int*   ei   = (const int*)d_in[1];       // int32 (JAX x64 disabled)
    const float* ew   = (const float*)d_in[2];
    const float* W    = (const float*)d_in[3];
    const float* aw   = (const float*)d_in[4];
    const float* bias = (const float*)d_in[5];
    float* out = (float*)d_out;
    int E = in_sizes[2];

    dim3 spmvBlk(64, 4);
    k_init  <<<HSIZE / 4 / 256, 256>>>(aw);
    k_insert<<<(E + 255) / 256, 256>>>(ei, E);
    k_scan  <<<1, 1024>>>();                    // needs rcnt (from insert) only
    k_deg   <<<(E + 255) / 256, 256>>>(ew, E);  // profiled slot (idx 3)
    k_fill  <<<(E + 255) / 256, 256>>>(ew, E);
    k_spmv1 <<<NNODES / 4, spmvBlk>>>(x);
    k_spmv2 <<<NNODES / 4, spmvBlk>>>(x);
    k_gemm  <<<NNODES / 16, 256>>>(x, W, bias, out);
}